// round 2
// baseline (speedup 1.0000x reference)
#include <cuda_runtime.h>

#define LW 49
#define DK 32
#define NH 8
#define NW 64
#define LP 52   // padded logits length (13 float4)

// Pre-gathered relative-position bias: bias[h][t*49+s]
__device__ float g_biasfull[NH * LW * LW];

__global__ void bias_gather_kernel(const float* __restrict__ table,
                                   const int* __restrict__ idx) {
    int i = blockIdx.x * blockDim.x + threadIdx.x;
    if (i < NH * LW * LW) {
        int h = i / (LW * LW);
        int e = i - h * (LW * LW);
        g_biasfull[i] = table[idx[e] * NH + h];
    }
}

__global__ __launch_bounds__(64, 8)
void win_attn_kernel(const float* __restrict__ q,
                     const float* __restrict__ k,
                     const float* __restrict__ mask,
                     float* __restrict__ out_score,
                     float* __restrict__ out_attn) {
    // SMEM: k row-major (s contiguous), k transposed (c contiguous), q, attn staging
    __shared__ float qs[DK * LP];
    __shared__ float ks[DK * LP];
    __shared__ float kT[LW * DK];
    __shared__ float a_s[LW * LW];

    const int bh  = blockIdx.x;          // b*8 + h
    const int h   = bh & 7;
    const int b   = bh >> 3;
    const int w   = b & (NW - 1);        // window index for mask
    const int tid = threadIdx.x;

    const float* __restrict__ qg = q + (size_t)bh * (DK * LW);
    const float* __restrict__ kg = k + (size_t)bh * (DK * LW);

    // Cooperative load of q,k tiles (1568 floats each) via float4 (392 each).
    for (int j = tid; j < 392; j += 64) {
        float4 qv = ((const float4*)qg)[j];
        float4 kv = ((const float4*)kg)[j];
        float qa[4] = {qv.x, qv.y, qv.z, qv.w};
        float ka[4] = {kv.x, kv.y, kv.z, kv.w};
        int e = j * 4;
        #pragma unroll
        for (int u = 0; u < 4; u++) {
            int ee = e + u;
            int c  = ee / LW;            // const-div -> mul/shift
            int t  = ee - c * LW;
            qs[c * LP + t] = qa[u];
            ks[c * LP + t] = ka[u];
            kT[t * DK + c] = ka[u];
        }
    }
    __syncthreads();

    if (tid < LW) {
        const int t = tid;
        float acc[LP];
        #pragma unroll
        for (int s = 0; s < LP; s++) acc[s] = 0.f;

        // Phase 1: logits row t  (q[:,t] . k[:,s] for all s)
        #pragma unroll 4
        for (int c = 0; c < DK; c++) {
            float qc = qs[c * LP + t];
            #pragma unroll
            for (int j = 0; j < 13; j++) {
                float4 kk = *(const float4*)&ks[c * LP + j * 4];
                acc[j * 4 + 0] += qc * kk.x;
                acc[j * 4 + 1] += qc * kk.y;
                acc[j * 4 + 2] += qc * kk.z;
                acc[j * 4 + 3] += qc * kk.w;
            }
        }

        // scale + bias + mask, thread-local softmax
        const float* __restrict__ bm = g_biasfull + (h * LW + t) * LW;
        const float* __restrict__ mm = mask + ((size_t)w * LW + t) * LW;
        const float scale = 0.17677669529663687f;  // 32^-0.5
        float mx = -1e30f;
        #pragma unroll
        for (int s = 0; s < LW; s++) {
            float v = acc[s] * scale + bm[s] + mm[s];
            acc[s] = v;
            mx = fmaxf(mx, v);
        }
        float sum = 0.f;
        #pragma unroll
        for (int s = 0; s < LW; s++) {
            float e = __expf(acc[s] - mx);
            acc[s] = e;
            sum += e;
        }
        float inv = 1.0f / sum;
        #pragma unroll
        for (int s = 0; s < LW; s++) {
            acc[s] *= inv;
            a_s[t * LW + s] = acc[s];
        }

        // Phase 2: score[c][t] = sum_s p[s] * k[c][s]   (V := K in reference)
        float acc2[DK];
        #pragma unroll
        for (int c = 0; c < DK; c++) acc2[c] = 0.f;

        #pragma unroll 2
        for (int s = 0; s < LW; s++) {
            float pa = acc[s];
            #pragma unroll
            for (int j = 0; j < 8; j++) {
                float4 kk = *(const float4*)&kT[s * DK + j * 4];
                acc2[j * 4 + 0] += pa * kk.x;
                acc2[j * 4 + 1] += pa * kk.y;
                acc2[j * 4 + 2] += pa * kk.z;
                acc2[j * 4 + 3] += pa * kk.w;
            }
        }

        float* __restrict__ og = out_score + (size_t)bh * (DK * LW);
        #pragma unroll
        for (int c = 0; c < DK; c++) og[c * LW + t] = acc2[c];
    }
    __syncthreads();

    // Coalesced attn write-out
    float* __restrict__ ag = out_attn + (size_t)bh * (LW * LW);
    for (int i = tid; i < LW * LW; i += 64) ag[i] = a_s[i];
}

extern "C" void kernel_launch(void* const* d_in, const int* in_sizes, int n_in,
                              void* d_out, int out_size) {
    const float* q     = (const float*)d_in[0];
    const float* k     = (const float*)d_in[1];
    // d_in[2] (v) is unused: the reference sets v := k
    const float* mask  = (const float*)d_in[3];
    const float* table = (const float*)d_in[4];
    const int*   idx   = (const int*)d_in[5];

    float* out       = (float*)d_out;
    float* out_score = out;                                   // 2048*256*49
    float* out_attn  = out + (size_t)2048 * 256 * 49;         // 2048*8*49*49

    bias_gather_kernel<<<(NH * LW * LW + 255) / 256, 256>>>(table, idx);
    win_attn_kernel<<<2048 * NH, 64>>>(q, k, mask, out_score, out_attn);
}

// round 6
// speedup vs baseline: 1.7188x; 1.7188x over previous
#include <cuda_runtime.h>

#define LW 49
#define DK 32
#define NH 8
#define NW 64
#define LP 52     // padded k/q row length (13 float4)
#define BMP 2404  // padded 49*49, float4-aligned stride

// Fused (bias + mask) for each of the 512 (h,w) combos, padded rows.
__device__ float g_bm[NH * NW * BMP];

// One block per (h,w): g_bm[h*NW+w][t*49+s] = table[idx[t*49+s]*NH+h] + mask[w][t*49+s]
__global__ void bm_prep_kernel(const float* __restrict__ table,
                               const int* __restrict__ idx,
                               const float* __restrict__ mask) {
    const int hw = blockIdx.x;          // h*NW + w
    const int h  = hw >> 6;
    const int w  = hw & (NW - 1);
    float* __restrict__ dst = g_bm + (size_t)hw * BMP;
    const float* __restrict__ mg = mask + (size_t)w * (LW * LW);
    for (int i = threadIdx.x; i < BMP; i += blockDim.x) {
        float v = 0.f;
        if (i < LW * LW) v = table[idx[i] * NH + h] + mg[i];
        dst[i] = v;
    }
}

__global__ __launch_bounds__(64, 8)
void win_attn_kernel(const float* __restrict__ q,
                     const float* __restrict__ k,
                     float* __restrict__ out_score,
                     float* __restrict__ out_attn) {
    __shared__ float qs[DK * LP];
    __shared__ float ks[DK * LP];
    __shared__ float bm[BMP];   // bias+mask; later reused as attn staging (row-local)

    const int bh  = blockIdx.x;          // b*8 + h
    const int h   = bh & 7;
    const int w   = (bh >> 3) & (NW - 1);
    const int tid = threadIdx.x;

    const float* __restrict__ qg = q + (size_t)bh * (DK * LW);
    const float* __restrict__ kg = k + (size_t)bh * (DK * LW);

    // Zero the 3-element padding tail of each q/k row (96 slots each).
    for (int i = tid; i < 96; i += 64) {
        int c = i / 3, r = i - c * 3;
        qs[c * LP + 49 + r] = 0.f;
        ks[c * LP + 49 + r] = 0.f;
    }

    // Stage q,k tiles (392 float4 each), de-interleave 49->52 stride.
    for (int j = tid; j < 392; j += 64) {
        float4 qv = ((const float4*)qg)[j];
        float4 kv = ((const float4*)kg)[j];
        float qa[4] = {qv.x, qv.y, qv.z, qv.w};
        float ka[4] = {kv.x, kv.y, kv.z, kv.w};
        int e = j * 4;
        #pragma unroll
        for (int u = 0; u < 4; u++) {
            int ee = e + u;
            int c  = ee / LW;
            int t  = ee - c * LW;
            qs[c * LP + t] = qa[u];
            ks[c * LP + t] = ka[u];
        }
    }

    // Stage fused bias+mask tile: coalesced float4 (601 of them).
    {
        const float* __restrict__ bmg = g_bm + (size_t)(h * NW + w) * BMP;
        for (int i4 = tid; i4 < BMP / 4; i4 += 64)
            ((float4*)bm)[i4] = ((const float4*)bmg)[i4];
    }
    __syncthreads();

    if (tid < LW) {
        const int t = tid;
        float acc[LP];
        #pragma unroll
        for (int s = 0; s < LP; s++) acc[s] = 0.f;

        // Phase 1: logits row t  (q[:,t] . k[:,s] for all s). k rows broadcast.
        #pragma unroll 4
        for (int c = 0; c < DK; c++) {
            float qc = qs[c * LP + t];
            #pragma unroll
            for (int j = 0; j < 13; j++) {
                float4 kk = *(const float4*)&ks[c * LP + j * 4];
                acc[j * 4 + 0] += qc * kk.x;
                acc[j * 4 + 1] += qc * kk.y;
                acc[j * 4 + 2] += qc * kk.z;
                acc[j * 4 + 3] += qc * kk.w;
            }
        }

        // scale + (bias+mask) from SMEM (conflict-free: stride 49 words), softmax
        const float scale = 0.17677669529663687f;  // 32^-0.5
        float* bmr = bm + t * LW;   // thread-private row (read bias+mask, write probs)
        float mx = -1e30f;
        #pragma unroll
        for (int s = 0; s < LW; s++) {
            float v = fmaf(acc[s], scale, bmr[s]);
            acc[s] = v;
            mx = fmaxf(mx, v);
        }
        float sum = 0.f;
        #pragma unroll
        for (int s = 0; s < LW; s++) {
            float e = __expf(acc[s] - mx);
            acc[s] = e;
            sum += e;
        }
        float inv = 1.0f / sum;
        #pragma unroll
        for (int s = 0; s < LW; s++) acc[s] *= inv;
        // acc[49..51] stayed 0 through phase 1 (zeroed k padding) — keep them 0.

        // Phase 2: score[c][t] = sum_s p[s] * k[c][s], k rows broadcast from ks.
        float* __restrict__ og = out_score + (size_t)bh * (DK * LW);
        #pragma unroll 2
        for (int c = 0; c < DK; c++) {
            float p0 = 0.f, p1 = 0.f, p2 = 0.f, p3 = 0.f;
            #pragma unroll
            for (int j = 0; j < 13; j++) {
                float4 kk = *(const float4*)&ks[c * LP + j * 4];
                p0 += acc[j * 4 + 0] * kk.x;
                p1 += acc[j * 4 + 1] * kk.y;
                p2 += acc[j * 4 + 2] * kk.z;
                p3 += acc[j * 4 + 3] * kk.w;
            }
            og[c * LW + t] = (p0 + p1) + (p2 + p3);
        }

        // Stash probability row into bm (this thread's row only — safe reuse).
        #pragma unroll
        for (int s = 0; s < LW; s++) bmr[s] = acc[s];
    }
    __syncthreads();

    // Coalesced attn write-out from SMEM.
    float* __restrict__ ag = out_attn + (size_t)bh * (LW * LW);
    for (int i = tid; i < LW * LW; i += 64) ag[i] = bm[i];
}

extern "C" void kernel_launch(void* const* d_in, const int* in_sizes, int n_in,
                              void* d_out, int out_size) {
    const float* q     = (const float*)d_in[0];
    const float* k     = (const float*)d_in[1];
    // d_in[2] (v) unused: reference sets v := k
    const float* mask  = (const float*)d_in[3];
    const float* table = (const float*)d_in[4];
    const int*   idx   = (const int*)d_in[5];

    float* out       = (float*)d_out;
    float* out_score = out;                            // 2048*256*49
    float* out_attn  = out + (size_t)2048 * 256 * 49;  // 2048*8*49*49

    bm_prep_kernel<<<NH * NW, 256>>>(table, idx, mask);
    win_attn_kernel<<<2048 * NH, 64>>>(q, k, out_score, out_attn);
}